// round 2
// baseline (speedup 1.0000x reference)
#include <cuda_runtime.h>

// VectorQuantization: N=32768 rows of D=64 vs K=1024 codes.
// out = [quantized (N*D) | indices as float (N) | commitment_loss (1)]
//
// R2: split-K over 4 block groups for occupancy; candidates reduced in a
// light epilogue kernel. Distance arithmetic bit-identical to R1.

#define NROWS 32768
#define D     64
#define K     1024
#define S     4              // K-splits
#define KSPL  (K / S)        // 256 codes per split
#define TC    64             // codes per shared tile
#define RPB   64             // rows per block == threads per block
#define EPB   256            // epilogue threads per block
#define NEPI  (NROWS / EPB)  // 128 epilogue blocks

__device__ float g_best[S * NROWS];
__device__ int   g_bidx[S * NROWS];
__device__ float g_partial[NEPI];

static __device__ __forceinline__ unsigned long long ffma2(unsigned long long a,
                                                           unsigned long long b,
                                                           unsigned long long c) {
    unsigned long long d;
    asm("fma.rn.f32x2 %0, %1, %2, %3;" : "=l"(d) : "l"(a), "l"(b), "l"(c));
    return d;
}
static __device__ __forceinline__ unsigned long long fadd2(unsigned long long a,
                                                           unsigned long long b) {
    unsigned long long d;
    asm("add.rn.f32x2 %0, %1, %2;" : "=l"(d) : "l"(a), "l"(b));
    return d;
}
static __device__ __forceinline__ unsigned long long pack2(float lo, float hi) {
    unsigned long long r;
    asm("mov.b64 %0, {%1, %2};" : "=l"(r) : "f"(lo), "f"(hi));
    return r;
}
static __device__ __forceinline__ void unpack2(unsigned long long v, float& lo, float& hi) {
    asm("mov.b64 {%0, %1}, %2;" : "=f"(lo), "=f"(hi) : "l"(v));
}

// ---- Kernel A: per-(row,split) argmin over 256 codes -----------------------
__global__ void __launch_bounds__(RPB) vq_main(const float* __restrict__ x,
                                               const float* __restrict__ w) {
    __shared__ float s_w[TC * D];   // 16 KB code tile
    __shared__ float s_wn[TC];

    const int tid    = threadIdx.x;
    const int split  = blockIdx.x & (S - 1);
    const int rowblk = blockIdx.x >> 2;
    const int row    = rowblk * RPB + tid;
    const int k0     = split * KSPL;

    const float4* xrow = reinterpret_cast<const float4*>(x + (size_t)row * D);

    // Row into registers as 32 packed f32x2 values; sequential ||x||^2
    // (identical instruction sequence to R1 -> identical rounding).
    unsigned long long xr[32];
    float xnorm = 0.f;
#pragma unroll
    for (int i = 0; i < 16; i++) {
        float4 v = xrow[i];
        xnorm = __fadd_rn(xnorm, __fmul_rn(v.x, v.x));
        xnorm = __fadd_rn(xnorm, __fmul_rn(v.y, v.y));
        xnorm = __fadd_rn(xnorm, __fmul_rn(v.z, v.z));
        xnorm = __fadd_rn(xnorm, __fmul_rn(v.w, v.w));
        xr[2 * i]     = pack2(v.x, v.y);
        xr[2 * i + 1] = pack2(v.z, v.w);
    }

    float best = 3.4e38f;
    int bidx = k0;

    for (int t = k0; t < k0 + KSPL; t += TC) {
        __syncthreads();  // previous tile fully consumed
        const float4* wt = reinterpret_cast<const float4*>(w + (size_t)t * D);
        float4* sw4 = reinterpret_cast<float4*>(s_w);
#pragma unroll
        for (int i = 0; i < 16; i++) sw4[tid + i * RPB] = wt[tid + i * RPB];
        __syncthreads();
        // ||w||^2 for code `tid` of this tile — same op sequence everywhere,
        // so every block computes bit-identical norms (no cross-block drift).
        {
            const float4* wr = reinterpret_cast<const float4*>(s_w + tid * D);
            float s = 0.f;
#pragma unroll
            for (int i = 0; i < 16; i++) {
                float4 v = wr[i];
                s = __fadd_rn(s, __fmul_rn(v.x, v.x));
                s = __fadd_rn(s, __fmul_rn(v.y, v.y));
                s = __fadd_rn(s, __fmul_rn(v.z, v.z));
                s = __fadd_rn(s, __fmul_rn(v.w, v.w));
            }
            s_wn[tid] = s;
        }
        __syncthreads();

#pragma unroll 2
        for (int kk = 0; kk < TC; kk++) {
            const ulonglong2* wrow =
                reinterpret_cast<const ulonglong2*>(s_w + kk * D);
            unsigned long long a0 = 0ull, a1 = 0ull, a2 = 0ull, a3 = 0ull;
#pragma unroll
            for (int j = 0; j < 8; j++) {
                ulonglong2 wv0 = wrow[2 * j];
                ulonglong2 wv1 = wrow[2 * j + 1];
                a0 = ffma2(xr[4 * j],     wv0.x, a0);
                a1 = ffma2(xr[4 * j + 1], wv0.y, a1);
                a2 = ffma2(xr[4 * j + 2], wv1.x, a2);
                a3 = ffma2(xr[4 * j + 3], wv1.y, a3);
            }
            a0 = fadd2(a0, a2);
            a1 = fadd2(a1, a3);
            a0 = fadd2(a0, a1);
            float dlo, dhi;
            unpack2(a0, dlo, dhi);
            float dot = __fadd_rn(dlo, dhi);
            // Same rounding as reference: (||x||^2 + ||e||^2) - (2.0 * dot).
            float dist = __fsub_rn(__fadd_rn(xnorm, s_wn[kk]),
                                   __fmul_rn(2.0f, dot));
            if (dist < best) { best = dist; bidx = t + kk; }  // first min wins
        }
    }

    g_best[split * NROWS + row] = best;
    g_bidx[split * NROWS + row] = bidx;
}

// ---- Kernel B: reduce splits, gather, STE output, loss partials ------------
__global__ void __launch_bounds__(EPB) vq_epi(const float* __restrict__ x,
                                              const float* __restrict__ w,
                                              float* __restrict__ out_q,
                                              float* __restrict__ out_idx,
                                              int has_idx) {
    __shared__ float s_red[EPB];
    const int tid = threadIdx.x;
    const int row = blockIdx.x * EPB + tid;

    float best = g_best[row];
    int bidx = g_bidx[row];
#pragma unroll
    for (int s = 1; s < S; s++) {
        float b = g_best[s * NROWS + row];
        int   i = g_bidx[s * NROWS + row];
        if (b < best) { best = b; bidx = i; }  // strict <: earlier split wins ties
    }

    const float4* wb   = reinterpret_cast<const float4*>(w + (size_t)bidx * D);
    const float4* xrow = reinterpret_cast<const float4*>(x + (size_t)row * D);
    float4* oq = reinterpret_cast<float4*>(out_q + (size_t)row * D);
    float lsum = 0.f;
#pragma unroll
    for (int i = 0; i < 16; i++) {
        float4 wv = wb[i];
        float4 xv = xrow[i];
        float4 dv, ov;
        dv.x = __fsub_rn(wv.x, xv.x);
        dv.y = __fsub_rn(wv.y, xv.y);
        dv.z = __fsub_rn(wv.z, xv.z);
        dv.w = __fsub_rn(wv.w, xv.w);
        ov.x = __fadd_rn(xv.x, dv.x);   // inputs + (quantized - inputs)
        ov.y = __fadd_rn(xv.y, dv.y);
        ov.z = __fadd_rn(xv.z, dv.z);
        ov.w = __fadd_rn(xv.w, dv.w);
        lsum += dv.x * dv.x + dv.y * dv.y + dv.z * dv.z + dv.w * dv.w;
        oq[i] = ov;
    }
    if (has_idx) out_idx[row] = (float)bidx;

    s_red[tid] = lsum;
    __syncthreads();
#pragma unroll
    for (int s = EPB / 2; s > 0; s >>= 1) {
        if (tid < s) s_red[tid] = __fadd_rn(s_red[tid], s_red[tid + s]);
        __syncthreads();
    }
    if (tid == 0) g_partial[blockIdx.x] = s_red[0];
}

// ---- Kernel C: final deterministic reduction -> commitment loss ------------
__global__ void vq_final(float* __restrict__ out_loss) {
    __shared__ float s[64];
    int tid = threadIdx.x;  // 64 threads
    float v = __fadd_rn(g_partial[tid], g_partial[tid + 64]);
    s[tid] = v;
    __syncthreads();
    for (int st = 32; st > 0; st >>= 1) {
        if (tid < st) s[tid] = __fadd_rn(s[tid], s[tid + st]);
        __syncthreads();
    }
    if (tid == 0) {
        float mean = s[0] / 2097152.0f;  // exact: power-of-two divisor
        *out_loss = 0.25f * (mean + mean);
    }
}

extern "C" void kernel_launch(void* const* d_in, const int* in_sizes, int n_in,
                              void* d_out, int out_size) {
    const float* x;
    const float* w;
    if (n_in >= 2 && in_sizes[0] == K * D && in_sizes[1] != K * D) {
        w = (const float*)d_in[0];
        x = (const float*)d_in[1];
    } else {
        x = (const float*)d_in[0];
        w = (const float*)d_in[1];
    }

    float* out = (float*)d_out;
    const long ND = (long)NROWS * D;
    if (out_size < ND) return;

    int has_idx  = out_size >= ND + NROWS;
    int has_loss = out_size >= ND + NROWS + 1;

    vq_main<<<(NROWS / RPB) * S, RPB>>>(x, w);
    vq_epi<<<NEPI, EPB>>>(x, w, out, out + ND, has_idx);
    if (has_loss) vq_final<<<1, 64>>>(out + ND + NROWS);
}

// round 3
// speedup vs baseline: 1.3042x; 1.3042x over previous
#include <cuda_runtime.h>

// VectorQuantization: N=32768 rows of D=64 vs K=1024 codes.
// out = [quantized (N*D) | indices as float (N) | commitment_loss (1)]
//
// R3: 2 rows per thread (x in registers) -> code-row LDS amortized 2x
//     (LDS:FFMA2 = 1:4). S=4 K-splits for warp count. Distance arithmetic
//     bit-identical to R1/R2 (which passed with rel_err 1.2e-7).

#define NROWS 32768
#define D     64
#define K     1024
#define S     4               // K-splits
#define KSPL  (K / S)         // 256 codes per split
#define TC    128             // codes per shared tile (2 tiles per split)
#define RPB   64              // threads per block
#define ROWSB (RPB * 2)       // rows per block = 128
#define NBLKM ((NROWS / ROWSB) * S)  // 1024 main blocks
#define EPB   256             // epilogue threads per block
#define NEPI  (NROWS / EPB)   // 128 epilogue blocks

__device__ float g_best[S * NROWS];
__device__ int   g_bidx[S * NROWS];
__device__ float g_partial[NEPI];

static __device__ __forceinline__ unsigned long long ffma2(unsigned long long a,
                                                           unsigned long long b,
                                                           unsigned long long c) {
    unsigned long long d;
    asm("fma.rn.f32x2 %0, %1, %2, %3;" : "=l"(d) : "l"(a), "l"(b), "l"(c));
    return d;
}
static __device__ __forceinline__ unsigned long long fadd2(unsigned long long a,
                                                           unsigned long long b) {
    unsigned long long d;
    asm("add.rn.f32x2 %0, %1, %2;" : "=l"(d) : "l"(a), "l"(b));
    return d;
}
static __device__ __forceinline__ unsigned long long pack2(float lo, float hi) {
    unsigned long long r;
    asm("mov.b64 %0, {%1, %2};" : "=l"(r) : "f"(lo), "f"(hi));
    return r;
}
static __device__ __forceinline__ void unpack2(unsigned long long v, float& lo, float& hi) {
    asm("mov.b64 {%0, %1}, %2;" : "=f"(lo), "=f"(hi) : "l"(v));
}

// ---- Kernel A: per-(row,split) argmin, 2 rows per thread -------------------
__global__ void __launch_bounds__(RPB) vq_main(const float* __restrict__ x,
                                               const float* __restrict__ w) {
    __shared__ float s_w[TC * D];   // 32 KB code tile
    __shared__ float s_wn[TC];

    const int tid    = threadIdx.x;
    const int split  = blockIdx.x & (S - 1);
    const int rowblk = blockIdx.x >> 2;
    const int row0   = rowblk * ROWSB + tid;
    const int row1   = row0 + RPB;
    const int k0     = split * KSPL;

    const float4* xrow0 = reinterpret_cast<const float4*>(x + (size_t)row0 * D);
    const float4* xrow1 = reinterpret_cast<const float4*>(x + (size_t)row1 * D);

    // Both rows into registers; sequential ||x||^2 (same rounding as R1).
    unsigned long long xr0[32], xr1[32];
    float xn0 = 0.f, xn1 = 0.f;
#pragma unroll
    for (int i = 0; i < 16; i++) {
        float4 v = xrow0[i];
        xn0 = __fadd_rn(xn0, __fmul_rn(v.x, v.x));
        xn0 = __fadd_rn(xn0, __fmul_rn(v.y, v.y));
        xn0 = __fadd_rn(xn0, __fmul_rn(v.z, v.z));
        xn0 = __fadd_rn(xn0, __fmul_rn(v.w, v.w));
        xr0[2 * i]     = pack2(v.x, v.y);
        xr0[2 * i + 1] = pack2(v.z, v.w);
    }
#pragma unroll
    for (int i = 0; i < 16; i++) {
        float4 v = xrow1[i];
        xn1 = __fadd_rn(xn1, __fmul_rn(v.x, v.x));
        xn1 = __fadd_rn(xn1, __fmul_rn(v.y, v.y));
        xn1 = __fadd_rn(xn1, __fmul_rn(v.z, v.z));
        xn1 = __fadd_rn(xn1, __fmul_rn(v.w, v.w));
        xr1[2 * i]     = pack2(v.x, v.y);
        xr1[2 * i + 1] = pack2(v.z, v.w);
    }

    float best0 = 3.4e38f, best1 = 3.4e38f;
    int bidx0 = k0, bidx1 = k0;

    for (int t = k0; t < k0 + KSPL; t += TC) {
        __syncthreads();  // previous tile fully consumed
        const float4* wt = reinterpret_cast<const float4*>(w + (size_t)t * D);
        float4* sw4 = reinterpret_cast<float4*>(s_w);
#pragma unroll
        for (int i = 0; i < 32; i++) sw4[tid + i * RPB] = wt[tid + i * RPB];
        __syncthreads();
        // ||w||^2, identical op sequence everywhere -> bit-identical norms.
#pragma unroll
        for (int c = 0; c < 2; c++) {
            const float4* wr = reinterpret_cast<const float4*>(s_w + (tid + c * RPB) * D);
            float s = 0.f;
#pragma unroll
            for (int i = 0; i < 16; i++) {
                float4 v = wr[i];
                s = __fadd_rn(s, __fmul_rn(v.x, v.x));
                s = __fadd_rn(s, __fmul_rn(v.y, v.y));
                s = __fadd_rn(s, __fmul_rn(v.z, v.z));
                s = __fadd_rn(s, __fmul_rn(v.w, v.w));
            }
            s_wn[tid + c * RPB] = s;
        }
        __syncthreads();

#pragma unroll 2
        for (int kk = 0; kk < TC; kk++) {
            const ulonglong2* wrow =
                reinterpret_cast<const ulonglong2*>(s_w + kk * D);
            unsigned long long a00 = 0ull, a01 = 0ull, a02 = 0ull, a03 = 0ull;
            unsigned long long a10 = 0ull, a11 = 0ull, a12 = 0ull, a13 = 0ull;
#pragma unroll
            for (int j = 0; j < 8; j++) {
                ulonglong2 wv0 = wrow[2 * j];
                ulonglong2 wv1 = wrow[2 * j + 1];
                a00 = ffma2(xr0[4 * j],     wv0.x, a00);
                a01 = ffma2(xr0[4 * j + 1], wv0.y, a01);
                a02 = ffma2(xr0[4 * j + 2], wv1.x, a02);
                a03 = ffma2(xr0[4 * j + 3], wv1.y, a03);
                a10 = ffma2(xr1[4 * j],     wv0.x, a10);
                a11 = ffma2(xr1[4 * j + 1], wv0.y, a11);
                a12 = ffma2(xr1[4 * j + 2], wv1.x, a12);
                a13 = ffma2(xr1[4 * j + 3], wv1.y, a13);
            }
            a00 = fadd2(a00, a02); a01 = fadd2(a01, a03); a00 = fadd2(a00, a01);
            a10 = fadd2(a10, a12); a11 = fadd2(a11, a13); a10 = fadd2(a10, a11);
            float lo, hi;
            unpack2(a00, lo, hi);
            float dot0 = __fadd_rn(lo, hi);
            unpack2(a10, lo, hi);
            float dot1 = __fadd_rn(lo, hi);
            float wn = s_wn[kk];
            // Same rounding as reference: (||x||^2 + ||e||^2) - (2.0 * dot).
            float d0 = __fsub_rn(__fadd_rn(xn0, wn), __fmul_rn(2.0f, dot0));
            float d1 = __fsub_rn(__fadd_rn(xn1, wn), __fmul_rn(2.0f, dot1));
            if (d0 < best0) { best0 = d0; bidx0 = t + kk; }  // first min wins
            if (d1 < best1) { best1 = d1; bidx1 = t + kk; }
        }
    }

    g_best[split * NROWS + row0] = best0;
    g_bidx[split * NROWS + row0] = bidx0;
    g_best[split * NROWS + row1] = best1;
    g_bidx[split * NROWS + row1] = bidx1;
}

// ---- Kernel B: reduce splits, gather, STE output, loss partials ------------
__global__ void __launch_bounds__(EPB) vq_epi(const float* __restrict__ x,
                                              const float* __restrict__ w,
                                              float* __restrict__ out_q,
                                              float* __restrict__ out_idx,
                                              int has_idx) {
    __shared__ float s_red[EPB];
    const int tid = threadIdx.x;
    const int row = blockIdx.x * EPB + tid;

    float best = g_best[row];
    int bidx = g_bidx[row];
#pragma unroll
    for (int s = 1; s < S; s++) {
        float b = g_best[s * NROWS + row];
        int   i = g_bidx[s * NROWS + row];
        if (b < best) { best = b; bidx = i; }  // strict <: earlier split wins ties
    }

    const float4* wb   = reinterpret_cast<const float4*>(w + (size_t)bidx * D);
    const float4* xrow = reinterpret_cast<const float4*>(x + (size_t)row * D);
    float4* oq = reinterpret_cast<float4*>(out_q + (size_t)row * D);
    float lsum = 0.f;
#pragma unroll
    for (int i = 0; i < 16; i++) {
        float4 wv = wb[i];
        float4 xv = xrow[i];
        float4 dv, ov;
        dv.x = __fsub_rn(wv.x, xv.x);
        dv.y = __fsub_rn(wv.y, xv.y);
        dv.z = __fsub_rn(wv.z, xv.z);
        dv.w = __fsub_rn(wv.w, xv.w);
        ov.x = __fadd_rn(xv.x, dv.x);   // inputs + (quantized - inputs)
        ov.y = __fadd_rn(xv.y, dv.y);
        ov.z = __fadd_rn(xv.z, dv.z);
        ov.w = __fadd_rn(xv.w, dv.w);
        lsum += dv.x * dv.x + dv.y * dv.y + dv.z * dv.z + dv.w * dv.w;
        oq[i] = ov;
    }
    if (has_idx) out_idx[row] = (float)bidx;

    s_red[tid] = lsum;
    __syncthreads();
#pragma unroll
    for (int s = EPB / 2; s > 0; s >>= 1) {
        if (tid < s) s_red[tid] = __fadd_rn(s_red[tid], s_red[tid + s]);
        __syncthreads();
    }
    if (tid == 0) g_partial[blockIdx.x] = s_red[0];
}

// ---- Kernel C: final deterministic reduction -> commitment loss ------------
__global__ void vq_final(float* __restrict__ out_loss) {
    __shared__ float s[64];
    int tid = threadIdx.x;  // 64 threads
    s[tid] = __fadd_rn(g_partial[tid], g_partial[tid + 64]);
    __syncthreads();
    for (int st = 32; st > 0; st >>= 1) {
        if (tid < st) s[tid] = __fadd_rn(s[tid], s[tid + st]);
        __syncthreads();
    }
    if (tid == 0) {
        float mean = s[0] / 2097152.0f;  // exact: power-of-two divisor
        *out_loss = 0.25f * (mean + mean);
    }
}

extern "C" void kernel_launch(void* const* d_in, const int* in_sizes, int n_in,
                              void* d_out, int out_size) {
    const float* x;
    const float* w;
    if (n_in >= 2 && in_sizes[0] == K * D && in_sizes[1] != K * D) {
        w = (const float*)d_in[0];
        x = (const float*)d_in[1];
    } else {
        x = (const float*)d_in[0];
        w = (const float*)d_in[1];
    }

    float* out = (float*)d_out;
    const long ND = (long)NROWS * D;
    if (out_size < ND) return;

    int has_idx  = out_size >= ND + NROWS;
    int has_loss = out_size >= ND + NROWS + 1;

    vq_main<<<NBLKM, RPB>>>(x, w);
    vq_epi<<<NEPI, EPB>>>(x, w, out, out + ND, has_idx);
    if (has_loss) vq_final<<<1, 64>>>(out + ND + NROWS);
}